// round 14
// baseline (speedup 1.0000x reference)
#include <cuda_runtime.h>
#include <cuda_bf16.h>
#include <cuda_fp8.h>
#include <cstdint>
#include <cstddef>

// ---------------------------------------------------------------------------
// d[n,c] = ||x_n||^2 + ||p_c||^2 - 2 * <x_n, p_c>
// x: [16384,1024] f32, p: [4096,1024] f32, out: [16384,4096] f32
//
// fp8 e4m3 mma.sync m16n8k32 (fp32 acc), mean-split hardening (p = 0.5 + r).
// R12 inner loop (interleaved [ldm][mma], 3-stage cp.async.bulk pipeline)
// made PERSISTENT: 296 CTAs (2/SM) walk tiles with the stage pipeline rolling
// continuously across tiles (producer 2 iterations ahead through the global
// block sequence) -> no per-tile prologue stall, no wave transitions.
// ---------------------------------------------------------------------------

static constexpr int N_ROWS = 16384;
static constexpr int C_ROWS = 4096;
static constexpr int DDIM   = 1024;

static constexpr int TILE_M = 128;
static constexpr int TILE_N = 128;
static constexpr int TILE_K = 128;                      // 128 fp8 = 128 B/row
static constexpr int K_TILES = DDIM / TILE_K;           // 8
static constexpr int STAGES  = 3;

static constexpr int M_TILES = N_ROWS / TILE_M;         // 128
static constexpr int NT_TILES = C_ROWS / TILE_N;        // 32
static constexpr int NTILES  = M_TILES * NT_TILES;      // 4096
static constexpr int GRID    = 296;                     // 2 CTAs x 148 SMs

static constexpr int BLOCK_BYTES  = TILE_M * TILE_K;    // 16384
static constexpr int STAGE_BYTES  = 2 * BLOCK_BYTES;    // 32768
static constexpr unsigned SMEM_DYN = STAGES * STAGE_BYTES + 1024;

// ---------------- device scratch (allocations are forbidden) ---------------
__device__ __align__(128) uint8_t g_A[(size_t)N_ROWS * DDIM];   // 16 MB fp8
__device__ __align__(128) uint8_t g_B[(size_t)C_ROWS * DDIM];   //  4 MB fp8
__device__ float g_xc[N_ROWS];    // ||x||^2 - sum(x)
__device__ float g_psq[C_ROWS];   // ||p||^2 exact
__device__ float g_sx[N_ROWS];    // 2 * amax_x / 448
__device__ float g_sp[C_ROWS];    //     amax_r / 448

// ------------------------------ helpers ------------------------------------
__device__ __forceinline__ uint32_t s2u(const void* p) {
    return (uint32_t)__cvta_generic_to_shared(p);
}
__device__ __forceinline__ uint32_t swz(uint32_t o) { return o ^ ((o >> 3) & 0x70u); }

__device__ __forceinline__ void mbar_init(uint32_t a, uint32_t n) {
    asm volatile("mbarrier.init.shared.b64 [%0], %1;" :: "r"(a), "r"(n) : "memory");
}
__device__ __forceinline__ void mbar_expect(uint32_t a, uint32_t tx) {
    asm volatile("mbarrier.arrive.expect_tx.shared.b64 _, [%0], %1;"
                 :: "r"(a), "r"(tx) : "memory");
}
__device__ __forceinline__ void mbar_arrive(uint32_t a) {
    asm volatile("mbarrier.arrive.shared.b64 _, [%0];" :: "r"(a) : "memory");
}
__device__ __forceinline__ void mbar_wait(uint32_t a, uint32_t phase) {
    asm volatile(
        "{\n\t.reg .pred P;\n"
        "W%=:\n\t"
        "mbarrier.try_wait.parity.acquire.cta.shared::cta.b64 P, [%0], %1, 0x989680;\n\t"
        "@P bra D%=;\n\t"
        "bra W%=;\n"
        "D%=:\n\t}"
        :: "r"(a), "r"(phase) : "memory");
}
__device__ __forceinline__ void bulk_g2s(uint32_t dst, const void* src,
                                         uint32_t bytes, uint32_t bar) {
    asm volatile(
        "cp.async.bulk.shared::cluster.global.mbarrier::complete_tx::bytes "
        "[%0], [%1], %2, [%3];"
        :: "r"(dst), "l"(src), "r"(bytes), "r"(bar) : "memory");
}
__device__ __forceinline__ void ldm_x4(uint32_t* r, uint32_t addr) {
    asm volatile("ldmatrix.sync.aligned.m8n8.x4.shared.b16 {%0,%1,%2,%3}, [%4];"
                 : "=r"(r[0]), "=r"(r[1]), "=r"(r[2]), "=r"(r[3]) : "r"(addr));
}
__device__ __forceinline__ void mma16832(float* c, const uint32_t* a,
                                         uint32_t b0, uint32_t b1) {
    asm volatile(
        "mma.sync.aligned.m16n8k32.row.col.f32.e4m3.e4m3.f32 "
        "{%0,%1,%2,%3}, {%4,%5,%6,%7}, {%8,%9}, {%0,%1,%2,%3};"
        : "+f"(c[0]), "+f"(c[1]), "+f"(c[2]), "+f"(c[3])
        : "r"(a[0]), "r"(a[1]), "r"(a[2]), "r"(a[3]), "r"(b0), "r"(b1));
}
__device__ __forceinline__ uint32_t qfp8x4(float4 f, float q) {
    __nv_fp8x4_e4m3 v(make_float4(f.x * q, f.y * q, f.z * q, f.w * q));
    return *reinterpret_cast<uint32_t*>(&v);
}

// ------ pre-pass: f32 -> scaled e4m3, TILED+SWIZZLED blocks + norms --------
__global__ void __launch_bounds__(128)
convq_kernel(const float* __restrict__ xsrc, const float* __restrict__ psrc) {
    const bool isx = (blockIdx.x < N_ROWS / 4);
    const int row  = (isx ? blockIdx.x : blockIdx.x - N_ROWS / 4) * 4
                   + (threadIdx.x >> 5);
    const int lane = threadIdx.x & 31;
    const float* src = isx ? xsrc : psrc;
    uint8_t* dst     = isx ? g_A : g_B;
    const float4* xr = reinterpret_cast<const float4*>(src + (size_t)row * DDIM);

    float4 f[2][4];
    float ss = 0.f, sm = 0.f, am = 0.f;
#pragma unroll
    for (int h = 0; h < 2; h++) {
        const int c = lane + h * 32;
#pragma unroll
        for (int j = 0; j < 4; j++) {
            float4 v = xr[c * 4 + j];
            ss += v.x * v.x + v.y * v.y + v.z * v.z + v.w * v.w;
            if (isx) {
                sm += v.x + v.y + v.z + v.w;
            } else {
                v.x -= 0.5f; v.y -= 0.5f; v.z -= 0.5f; v.w -= 0.5f;
            }
            f[h][j] = v;
            am = fmaxf(am, fmaxf(fmaxf(fabsf(v.x), fabsf(v.y)),
                                 fmaxf(fabsf(v.z), fabsf(v.w))));
        }
    }
#pragma unroll
    for (int o = 16; o; o >>= 1) {
        ss += __shfl_xor_sync(0xffffffffu, ss, o);
        am = fmaxf(am, __shfl_xor_sync(0xffffffffu, am, o));
        sm += __shfl_xor_sync(0xffffffffu, sm, o);
    }
    am = fmaxf(am, 1e-30f);
    const float q = 448.f / am;

    const int rt = row >> 7, rr = row & 127;
#pragma unroll
    for (int h = 0; h < 2; h++) {
        const int c  = lane + h * 32;
        const int kt = c >> 3;
        const int cu = (c & 7) * 16;
        uint4 v;
        v.x = qfp8x4(f[h][0], q); v.y = qfp8x4(f[h][1], q);
        v.z = qfp8x4(f[h][2], q); v.w = qfp8x4(f[h][3], q);
        uint8_t* blk = dst + ((size_t)rt * K_TILES + kt) * BLOCK_BYTES;
        *reinterpret_cast<uint4*>(blk + swz((uint32_t)(rr * 128 + cu))) = v;
    }
    if (lane == 0) {
        if (isx) {
            g_xc[row] = ss - sm;
            g_sx[row] = 2.f * am * (1.f / 448.f);
        } else {
            g_psq[row] = ss;
            g_sp[row]  = am * (1.f / 448.f);
        }
    }
}

// --------------------------- main GEMM kernel ------------------------------
// Persistent: 296 CTAs x 256 threads (8 warps, 2M x 4N, warp tile 64x32),
// 2 CTAs/SM. Pipeline state rolls continuously across tiles.
__global__ void __launch_bounds__(256, 2)
gemm_kernel(float* __restrict__ out) {
    extern __shared__ char smem[];
    __shared__ __align__(8) uint64_t s_bar[2 * STAGES];   // FULL[3], EMPTY[3]

    const uint32_t sbase = (s2u(smem) + 1023u) & ~1023u;
    const uint32_t FULL  = s2u(s_bar);
    const uint32_t EMPTY = FULL + STAGES * 8;

    const int tid  = threadIdx.x;
    const int wid  = tid >> 5;
    const int lane = tid & 31;
    const int wm = (wid & 1) * 64;
    const int wn = (wid >> 1) * 32;

    if (tid == 0) {
#pragma unroll
        for (int s = 0; s < STAGES; s++) {
            mbar_init(FULL + s * 8, 1);            // tx-based completion
            mbar_init(EMPTY + s * 8, 8);           // one arrive per warp
        }
    }
    __syncthreads();

    // ---- producer walker state (meaningful in thread 0 only) --------------
    int ptile = blockIdx.x, pkt = 0;               // next block to fetch
    int pst = 0, pph = 1;                          // stage/phase state machine

    // two prologue refills (EMPTY waits pass instantly at phase 1)
    if (tid == 0) {
#pragma unroll
        for (int i = 0; i < 2; i++) {
            mbar_wait(EMPTY + pst * 8, (uint32_t)pph);
            const uint32_t fb  = FULL + pst * 8;
            const uint32_t dst = sbase + pst * STAGE_BYTES;
            mbar_expect(fb, STAGE_BYTES);
            const uint8_t* Asrc = g_A + ((size_t)(ptile >> 5) * K_TILES + pkt) * BLOCK_BYTES;
            const uint8_t* Bsrc = g_B + ((size_t)(ptile & 31) * K_TILES + pkt) * BLOCK_BYTES;
            bulk_g2s(dst,               Asrc, BLOCK_BYTES, fb);
            bulk_g2s(dst + BLOCK_BYTES, Bsrc, BLOCK_BYTES, fb);
            if (++pst == STAGES) { pst = 0; pph ^= 1; }
            if (++pkt == K_TILES) { pkt = 0; ptile += GRID; }
        }
    }

    const int lrow = lane & 15;
    const int lkb  = (lane >> 4) * 16;

    // XOR-folded relative addresses: addr = sX + (R ^ (kk<<5))
    uint32_t AR[4], BR[2];
#pragma unroll
    for (int mi = 0; mi < 4; mi++) {
        const int r = wm + mi * 16 + lrow;
        AR[mi] = (uint32_t)(r * 128) + ((uint32_t)lkb ^ (uint32_t)((r & 7) * 16));
    }
#pragma unroll
    for (int nj = 0; nj < 2; nj++) {
        const int r = wn + nj * 16 + lrow;
        BR[nj] = (uint32_t)(r * 128) + ((uint32_t)lkb ^ (uint32_t)((r & 7) * 16));
    }

    float acc[4][4][4];
    uint32_t a[4][4];       // A fragments (reloaded per k32 step)
    uint32_t b[2][2][4];    // B fragments, double-buffered across k32 steps

    int cst = 0;            // consumer stage
    uint32_t cph = 0;       // consumer phase

    for (int tile = blockIdx.x; tile < NTILES; tile += GRID) {
#pragma unroll
        for (int i = 0; i < 4; i++)
#pragma unroll
            for (int j = 0; j < 4; j++)
#pragma unroll
                for (int r = 0; r < 4; r++) acc[i][j][r] = 0.f;

        for (int kt = 0; kt < K_TILES; kt++) {
            // ---- producer: one refill per consumer iteration, 2 ahead ----
            if (tid == 0 && ptile < NTILES) {
                mbar_wait(EMPTY + pst * 8, (uint32_t)pph);
                const uint32_t fb  = FULL + pst * 8;
                const uint32_t dst = sbase + pst * STAGE_BYTES;
                mbar_expect(fb, STAGE_BYTES);
                const uint8_t* Asrc = g_A + ((size_t)(ptile >> 5) * K_TILES + pkt) * BLOCK_BYTES;
                const uint8_t* Bsrc = g_B + ((size_t)(ptile & 31) * K_TILES + pkt) * BLOCK_BYTES;
                bulk_g2s(dst,               Asrc, BLOCK_BYTES, fb);
                bulk_g2s(dst + BLOCK_BYTES, Bsrc, BLOCK_BYTES, fb);
                if (++pst == STAGES) { pst = 0; pph ^= 1; }
                if (++pkt == K_TILES) { pkt = 0; ptile += GRID; }
            }

            // ---- consumer: interleaved [ldm][mma] stream (R12) -----------
            mbar_wait(FULL + cst * 8, cph);
            const uint32_t sA = sbase + cst * STAGE_BYTES;
            const uint32_t sB = sA + BLOCK_BYTES;

            // prime B bank 0 for kk=0
            ldm_x4(b[0][0], sB + BR[0]);
            ldm_x4(b[0][1], sB + BR[1]);

#pragma unroll
            for (int kk = 0; kk < 4; kk++) {
                const int cur = kk & 1;
                const int nxt = cur ^ 1;
                const uint32_t kx  = (uint32_t)(kk << 5);
                const uint32_t kxn = (uint32_t)((kk + 1) << 5);

                ldm_x4(a[0], sA + (AR[0] ^ kx));
#pragma unroll
                for (int mi = 0; mi < 4; mi++) {
                    if (mi < 3) {
                        ldm_x4(a[mi + 1], sA + (AR[mi + 1] ^ kx));
                    } else if (kk < 3) {
                        ldm_x4(b[nxt][0], sB + (BR[0] ^ kxn));
                        ldm_x4(b[nxt][1], sB + (BR[1] ^ kxn));
                    } else if (lane == 0) {
                        mbar_arrive(EMPTY + cst * 8);      // stage reads done
                    }
#pragma unroll
                    for (int nj = 0; nj < 2; nj++) {
                        mma16832(acc[mi][2 * nj + 0], a[mi],
                                 b[cur][nj][0], b[cur][nj][2]);
                        mma16832(acc[mi][2 * nj + 1], a[mi],
                                 b[cur][nj][1], b[cur][nj][3]);
                    }
                }
            }
            if (++cst == STAGES) { cst = 0; cph ^= 1; }
        }

        // ---- fused dequant epilogue: out = xc + psq - sx*sp*acc ----------
        const int m0 = (tile >> 5) * TILE_M;
        const int n0 = (tile & 31) * TILE_N;
        const int tr = lane >> 2;
        const int tc = (lane & 3) * 2;
#pragma unroll
        for (int mi = 0; mi < 4; mi++) {
            const int gm0 = m0 + wm + mi * 16 + tr;
            const float xc0 = g_xc[gm0],     sx0 = g_sx[gm0];
            const float xc1 = g_xc[gm0 + 8], sx1 = g_sx[gm0 + 8];
            float* o0 = out + (size_t)gm0 * C_ROWS + n0 + wn;
            float* o1 = o0 + (size_t)8 * C_ROWS;
#pragma unroll
            for (int ni = 0; ni < 4; ni++) {
                const int gc = n0 + wn + ni * 8 + tc;
                const float pq0 = __ldg(g_psq + gc),     sp0 = __ldg(g_sp + gc);
                const float pq1 = __ldg(g_psq + gc + 1), sp1 = __ldg(g_sp + gc + 1);
                float2 r0, r1;
                r0.x = fmaf(-sx0 * sp0, acc[mi][ni][0], xc0 + pq0);
                r0.y = fmaf(-sx0 * sp1, acc[mi][ni][1], xc0 + pq1);
                r1.x = fmaf(-sx1 * sp0, acc[mi][ni][2], xc1 + pq0);
                r1.y = fmaf(-sx1 * sp1, acc[mi][ni][3], xc1 + pq1);
                *reinterpret_cast<float2*>(o0 + ni * 8 + tc) = r0;
                *reinterpret_cast<float2*>(o1 + ni * 8 + tc) = r1;
            }
        }
    }
}

// ------------------------------- launch ------------------------------------
extern "C" void kernel_launch(void* const* d_in, const int* in_sizes, int n_in,
                              void* d_out, int out_size) {
    const float* x = (const float*)d_in[0];       // [16384, 1024]
    const float* p = (const float*)d_in[1];       // [4096, 1024]
    float* out = (float*)d_out;                   // [16384, 4096]

    cudaFuncSetAttribute(gemm_kernel,
                         cudaFuncAttributeMaxDynamicSharedMemorySize, SMEM_DYN);

    convq_kernel<<<(N_ROWS + C_ROWS) / 4, 128>>>(x, p);
    gemm_kernel<<<GRID, 256, SMEM_DYN>>>(out);
}

// round 15
// speedup vs baseline: 1.1466x; 1.1466x over previous
#include <cuda_runtime.h>
#include <cuda_bf16.h>
#include <cuda_fp8.h>
#include <cstdint>
#include <cstddef>

// ---------------------------------------------------------------------------
// d[n,c] = ||x_n||^2 + ||p_c||^2 - 2 * <x_n, p_c>
// x: [16384,1024] f32, p: [4096,1024] f32, out: [16384,4096] f32
//
// fp8 e4m3 mma.sync m16n8k32 (fp32 acc), mean-split hardening (p = 0.5 + r).
// R12 structure (4096 CTAs, 2/SM, 3-stage cp.async.bulk + mbarrier pipeline,
// interleaved [ldm][mma] stream) with A fragments DOUBLE-BUFFERED across k32
// steps: every ldmatrix now lands a full kk (~256cy) before its mma consumes
// it, hiding crossbar-contended LDS latency.
// ---------------------------------------------------------------------------

static constexpr int N_ROWS = 16384;
static constexpr int C_ROWS = 4096;
static constexpr int DDIM   = 1024;

static constexpr int TILE_M = 128;
static constexpr int TILE_N = 128;
static constexpr int TILE_K = 128;                      // 128 fp8 = 128 B/row
static constexpr int K_TILES = DDIM / TILE_K;           // 8
static constexpr int STAGES  = 3;

static constexpr int BLOCK_BYTES  = TILE_M * TILE_K;    // 16384
static constexpr int STAGE_BYTES  = 2 * BLOCK_BYTES;    // 32768
static constexpr unsigned SMEM_DYN = STAGES * STAGE_BYTES + 1024;

// ---------------- device scratch (allocations are forbidden) ---------------
__device__ __align__(128) uint8_t g_A[(size_t)N_ROWS * DDIM];   // 16 MB fp8
__device__ __align__(128) uint8_t g_B[(size_t)C_ROWS * DDIM];   //  4 MB fp8
__device__ float g_xc[N_ROWS];    // ||x||^2 - sum(x)
__device__ float g_psq[C_ROWS];   // ||p||^2 exact
__device__ float g_sx[N_ROWS];    // 2 * amax_x / 448
__device__ float g_sp[C_ROWS];    //     amax_r / 448

// ------------------------------ helpers ------------------------------------
__device__ __forceinline__ uint32_t s2u(const void* p) {
    return (uint32_t)__cvta_generic_to_shared(p);
}
__device__ __forceinline__ uint32_t swz(uint32_t o) { return o ^ ((o >> 3) & 0x70u); }

__device__ __forceinline__ void mbar_init(uint32_t a, uint32_t n) {
    asm volatile("mbarrier.init.shared.b64 [%0], %1;" :: "r"(a), "r"(n) : "memory");
}
__device__ __forceinline__ void mbar_expect(uint32_t a, uint32_t tx) {
    asm volatile("mbarrier.arrive.expect_tx.shared.b64 _, [%0], %1;"
                 :: "r"(a), "r"(tx) : "memory");
}
__device__ __forceinline__ void mbar_arrive(uint32_t a) {
    asm volatile("mbarrier.arrive.shared.b64 _, [%0];" :: "r"(a) : "memory");
}
__device__ __forceinline__ void mbar_wait(uint32_t a, uint32_t phase) {
    asm volatile(
        "{\n\t.reg .pred P;\n"
        "W%=:\n\t"
        "mbarrier.try_wait.parity.acquire.cta.shared::cta.b64 P, [%0], %1, 0x989680;\n\t"
        "@P bra D%=;\n\t"
        "bra W%=;\n"
        "D%=:\n\t}"
        :: "r"(a), "r"(phase) : "memory");
}
__device__ __forceinline__ void bulk_g2s(uint32_t dst, const void* src,
                                         uint32_t bytes, uint32_t bar) {
    asm volatile(
        "cp.async.bulk.shared::cluster.global.mbarrier::complete_tx::bytes "
        "[%0], [%1], %2, [%3];"
        :: "r"(dst), "l"(src), "r"(bytes), "r"(bar) : "memory");
}
__device__ __forceinline__ void ldm_x4(uint32_t* r, uint32_t addr) {
    asm volatile("ldmatrix.sync.aligned.m8n8.x4.shared.b16 {%0,%1,%2,%3}, [%4];"
                 : "=r"(r[0]), "=r"(r[1]), "=r"(r[2]), "=r"(r[3]) : "r"(addr));
}
__device__ __forceinline__ void mma16832(float* c, const uint32_t* a,
                                         uint32_t b0, uint32_t b1) {
    asm volatile(
        "mma.sync.aligned.m16n8k32.row.col.f32.e4m3.e4m3.f32 "
        "{%0,%1,%2,%3}, {%4,%5,%6,%7}, {%8,%9}, {%0,%1,%2,%3};"
        : "+f"(c[0]), "+f"(c[1]), "+f"(c[2]), "+f"(c[3])
        : "r"(a[0]), "r"(a[1]), "r"(a[2]), "r"(a[3]), "r"(b0), "r"(b1));
}
__device__ __forceinline__ uint32_t qfp8x4(float4 f, float q) {
    __nv_fp8x4_e4m3 v(make_float4(f.x * q, f.y * q, f.z * q, f.w * q));
    return *reinterpret_cast<uint32_t*>(&v);
}

// ------ pre-pass: f32 -> scaled e4m3, TILED+SWIZZLED blocks + norms --------
__global__ void __launch_bounds__(128)
convq_kernel(const float* __restrict__ xsrc, const float* __restrict__ psrc) {
    const bool isx = (blockIdx.x < N_ROWS / 4);
    const int row  = (isx ? blockIdx.x : blockIdx.x - N_ROWS / 4) * 4
                   + (threadIdx.x >> 5);
    const int lane = threadIdx.x & 31;
    const float* src = isx ? xsrc : psrc;
    uint8_t* dst     = isx ? g_A : g_B;
    const float4* xr = reinterpret_cast<const float4*>(src + (size_t)row * DDIM);

    float4 f[2][4];
    float ss = 0.f, sm = 0.f, am = 0.f;
#pragma unroll
    for (int h = 0; h < 2; h++) {
        const int c = lane + h * 32;
#pragma unroll
        for (int j = 0; j < 4; j++) {
            float4 v = xr[c * 4 + j];
            ss += v.x * v.x + v.y * v.y + v.z * v.z + v.w * v.w;
            if (isx) {
                sm += v.x + v.y + v.z + v.w;
            } else {
                v.x -= 0.5f; v.y -= 0.5f; v.z -= 0.5f; v.w -= 0.5f;
            }
            f[h][j] = v;
            am = fmaxf(am, fmaxf(fmaxf(fabsf(v.x), fabsf(v.y)),
                                 fmaxf(fabsf(v.z), fabsf(v.w))));
        }
    }
#pragma unroll
    for (int o = 16; o; o >>= 1) {
        ss += __shfl_xor_sync(0xffffffffu, ss, o);
        am = fmaxf(am, __shfl_xor_sync(0xffffffffu, am, o));
        sm += __shfl_xor_sync(0xffffffffu, sm, o);
    }
    am = fmaxf(am, 1e-30f);
    const float q = 448.f / am;

    const int rt = row >> 7, rr = row & 127;
#pragma unroll
    for (int h = 0; h < 2; h++) {
        const int c  = lane + h * 32;
        const int kt = c >> 3;
        const int cu = (c & 7) * 16;
        uint4 v;
        v.x = qfp8x4(f[h][0], q); v.y = qfp8x4(f[h][1], q);
        v.z = qfp8x4(f[h][2], q); v.w = qfp8x4(f[h][3], q);
        uint8_t* blk = dst + ((size_t)rt * K_TILES + kt) * BLOCK_BYTES;
        *reinterpret_cast<uint4*>(blk + swz((uint32_t)(rr * 128 + cu))) = v;
    }
    if (lane == 0) {
        if (isx) {
            g_xc[row] = ss - sm;
            g_sx[row] = 2.f * am * (1.f / 448.f);
        } else {
            g_psq[row] = ss;
            g_sp[row]  = am * (1.f / 448.f);
        }
    }
}

// --------------------------- main GEMM kernel ------------------------------
// CTA: 256 threads = 8 warps (2M x 4N); warp tile 64x32; 2 CTAs/SM.
__global__ void __launch_bounds__(256, 2)
gemm_kernel(float* __restrict__ out) {
    extern __shared__ char smem[];
    __shared__ __align__(8) uint64_t s_bar[2 * STAGES];   // FULL[3], EMPTY[3]

    const uint32_t sbase = (s2u(smem) + 1023u) & ~1023u;
    const uint32_t FULL  = s2u(s_bar);
    const uint32_t EMPTY = FULL + STAGES * 8;

    const int tid  = threadIdx.x;
    const int wid  = tid >> 5;
    const int lane = tid & 31;
    const int wm = (wid & 1) * 64;
    const int wn = (wid >> 1) * 32;

    const uint8_t* Ag = g_A + (size_t)blockIdx.x * K_TILES * BLOCK_BYTES;
    const uint8_t* Bg = g_B + (size_t)blockIdx.y * K_TILES * BLOCK_BYTES;

    if (tid == 0) {
#pragma unroll
        for (int s = 0; s < STAGES; s++) {
            mbar_init(FULL + s * 8, 1);            // tx-based completion
            mbar_init(EMPTY + s * 8, 8);           // one arrive per warp
        }
    }
    __syncthreads();

    if (tid == 0) {
#pragma unroll
        for (int s = 0; s < STAGES - 1; s++) {
            const uint32_t fb  = FULL + s * 8;
            const uint32_t dst = sbase + s * STAGE_BYTES;
            mbar_expect(fb, STAGE_BYTES);
            bulk_g2s(dst,               Ag + (size_t)s * BLOCK_BYTES, BLOCK_BYTES, fb);
            bulk_g2s(dst + BLOCK_BYTES, Bg + (size_t)s * BLOCK_BYTES, BLOCK_BYTES, fb);
        }
    }

    float acc[4][4][4];
#pragma unroll
    for (int i = 0; i < 4; i++)
#pragma unroll
        for (int j = 0; j < 4; j++)
#pragma unroll
            for (int r = 0; r < 4; r++) acc[i][j][r] = 0.f;

    const int lrow = lane & 15;
    const int lkb  = (lane >> 4) * 16;

    // Base relative addresses. For A, rows wm+mi*16+lrow share (row&7), so
    // AR(mi) = AR0 + mi*2048 and the kk XOR distributes: (AR0+mi*2048)^kx ==
    // (AR0^kx)+mi*2048 (kx bits 5-6 disjoint from mi*2048 bits >= 11).
    uint32_t AR0, BR0;
    {
        const int ra = wm + lrow;
        AR0 = (uint32_t)(ra * 128) + ((uint32_t)lkb ^ (uint32_t)((ra & 7) * 16));
        const int rb = wn + lrow;
        BR0 = (uint32_t)(rb * 128) + ((uint32_t)lkb ^ (uint32_t)((rb & 7) * 16));
    }

    uint32_t a[2][4][4];    // A fragments, double-buffered across k32 steps
    uint32_t b[2][2][4];    // B fragments, double-buffered across k32 steps

    int pst = STAGES - 1, pph = 1;                 // producer cursor
    int cst = 0, cph = 0;                          // consumer cursor

    for (int kt = 0; kt < K_TILES; kt++) {
        // ---- producer: refill stage for kt+STAGES-1 ----------------------
        if (tid == 0 && kt + STAGES - 1 < K_TILES) {
            const int kf = kt + STAGES - 1;
            mbar_wait(EMPTY + pst * 8, (uint32_t)pph);
            const uint32_t fb  = FULL + pst * 8;
            const uint32_t dst = sbase + pst * STAGE_BYTES;
            mbar_expect(fb, STAGE_BYTES);
            bulk_g2s(dst,               Ag + (size_t)kf * BLOCK_BYTES, BLOCK_BYTES, fb);
            bulk_g2s(dst + BLOCK_BYTES, Bg + (size_t)kf * BLOCK_BYTES, BLOCK_BYTES, fb);
            if (++pst == STAGES) { pst = 0; pph ^= 1; }
        }

        // ---- consumer: interleaved [ldm][mma], all frags one kk ahead ----
        mbar_wait(FULL + cst * 8, (uint32_t)cph);
        const uint32_t sA = sbase + cst * STAGE_BYTES;
        const uint32_t sB = sA + BLOCK_BYTES;

        // prime: all kk=0 fragments (6 LDSM, once per kt)
        {
            const uint32_t av = sA + AR0;
            const uint32_t bv = sB + BR0;
            ldm_x4(b[0][0], bv);
            ldm_x4(b[0][1], bv + 2048);
            ldm_x4(a[0][0], av);
            ldm_x4(a[0][1], av + 2048);
            ldm_x4(a[0][2], av + 4096);
            ldm_x4(a[0][3], av + 6144);
        }

#pragma unroll
        for (int kk = 0; kk < 4; kk++) {
            const int cur = kk & 1;
            const int nxt = cur ^ 1;
            const uint32_t avn = sA + (AR0 ^ (uint32_t)((kk + 1) << 5));
            const uint32_t bvn = sB + (BR0 ^ (uint32_t)((kk + 1) << 5));

#pragma unroll
            for (int mi = 0; mi < 4; mi++) {
                if (kk < 3) {                      // prefetch kk+1 fragments
                    ldm_x4(a[nxt][mi], avn + (uint32_t)(mi * 2048));
                    if (mi == 2) ldm_x4(b[nxt][0], bvn);
                    if (mi == 3) ldm_x4(b[nxt][1], bvn + 2048);
                } else if (mi == 3 && lane == 0) {
                    mbar_arrive(EMPTY + cst * 8);  // stage reads done
                }
#pragma unroll
                for (int nj = 0; nj < 2; nj++) {
                    mma16832(acc[mi][2 * nj + 0], a[cur][mi],
                             b[cur][nj][0], b[cur][nj][2]);
                    mma16832(acc[mi][2 * nj + 1], a[cur][mi],
                             b[cur][nj][1], b[cur][nj][3]);
                }
            }
        }
        if (++cst == STAGES) { cst = 0; cph ^= 1; }
    }

    // ---- fused dequant epilogue: out = xc + psq - sx*sp*acc  (x2 in sx) ----
    const int m0 = blockIdx.x * TILE_M;
    const int n0 = blockIdx.y * TILE_N;
    const int tr = lane >> 2;
    const int tc = (lane & 3) * 2;
#pragma unroll
    for (int mi = 0; mi < 4; mi++) {
        const int gm0 = m0 + wm + mi * 16 + tr;
        const float xc0 = g_xc[gm0],     sx0 = g_sx[gm0];
        const float xc1 = g_xc[gm0 + 8], sx1 = g_sx[gm0 + 8];
        float* o0 = out + (size_t)gm0 * C_ROWS + n0 + wn;
        float* o1 = o0 + (size_t)8 * C_ROWS;
#pragma unroll
        for (int ni = 0; ni < 4; ni++) {
            const int gc = n0 + wn + ni * 8 + tc;
            const float pq0 = __ldg(g_psq + gc),     sp0 = __ldg(g_sp + gc);
            const float pq1 = __ldg(g_psq + gc + 1), sp1 = __ldg(g_sp + gc + 1);
            float2 r0, r1;
            r0.x = fmaf(-sx0 * sp0, acc[mi][ni][0], xc0 + pq0);
            r0.y = fmaf(-sx0 * sp1, acc[mi][ni][1], xc0 + pq1);
            r1.x = fmaf(-sx1 * sp0, acc[mi][ni][2], xc1 + pq0);
            r1.y = fmaf(-sx1 * sp1, acc[mi][ni][3], xc1 + pq1);
            *reinterpret_cast<float2*>(o0 + ni * 8 + tc) = r0;
            *reinterpret_cast<float2*>(o1 + ni * 8 + tc) = r1;
        }
    }
}

// ------------------------------- launch ------------------------------------
extern "C" void kernel_launch(void* const* d_in, const int* in_sizes, int n_in,
                              void* d_out, int out_size) {
    const float* x = (const float*)d_in[0];       // [16384, 1024]
    const float* p = (const float*)d_in[1];       // [4096, 1024]
    float* out = (float*)d_out;                   // [16384, 4096]

    cudaFuncSetAttribute(gemm_kernel,
                         cudaFuncAttributeMaxDynamicSharedMemorySize, SMEM_DYN);

    convq_kernel<<<(N_ROWS + C_ROWS) / 4, 128>>>(x, p);
    gemm_kernel<<<dim3(N_ROWS / TILE_M, C_ROWS / TILE_N), 256, SMEM_DYN>>>(out);
}

// round 16
// speedup vs baseline: 1.1575x; 1.0095x over previous
#include <cuda_runtime.h>
#include <cuda_bf16.h>
#include <cuda_fp8.h>
#include <cstdint>
#include <cstddef>

// ---------------------------------------------------------------------------
// d[n,c] = ||x_n||^2 + ||p_c||^2 - 2 * <x_n, p_c>
// x: [16384,1024] f32, p: [4096,1024] f32, out: [16384,4096] f32
//
// fp8 e4m3 mma.sync m16n8k32 (fp32 acc), mean-split hardening (p = 0.5 + r).
// R12 inner loop (interleaved [ldm][mma], 3-stage cp.async.bulk pipeline)
// at HIGHER scheduler occupancy: 3 CTAs/SM x 128 threads (4 warps), CTA tile
// 128x64, warp tile 64x32 unchanged -> 3 warps/SMSP (was 2) to fill issue
// gaps; smem traffic/SM drops 256->216KB per kt; CTAs naturally desynced.
// ---------------------------------------------------------------------------

static constexpr int N_ROWS = 16384;
static constexpr int C_ROWS = 4096;
static constexpr int DDIM   = 1024;

static constexpr int TILE_M = 128;
static constexpr int TILE_N = 64;
static constexpr int TILE_K = 128;                      // 128 fp8 = 128 B/row
static constexpr int K_TILES = DDIM / TILE_K;           // 8
static constexpr int STAGES  = 3;

static constexpr int A_BLOCK = TILE_M * TILE_K;         // 16384
static constexpr int B_BLOCK = TILE_N * TILE_K;         // 8192
static constexpr int STAGE_BYTES = A_BLOCK + B_BLOCK;   // 24576
static constexpr unsigned SMEM_DYN = STAGES * STAGE_BYTES + 1024;  // 74752

// ---------------- device scratch (allocations are forbidden) ---------------
// g_A: [128][8][128x128B swizzled]; g_B: [64][8][64x128B swizzled]
__device__ __align__(128) uint8_t g_A[(size_t)N_ROWS * DDIM];   // 16 MB fp8
__device__ __align__(128) uint8_t g_B[(size_t)C_ROWS * DDIM];   //  4 MB fp8
__device__ float g_xc[N_ROWS];    // ||x||^2 - sum(x)
__device__ float g_psq[C_ROWS];   // ||p||^2 exact
__device__ float g_sx[N_ROWS];    // 2 * amax_x / 448
__device__ float g_sp[C_ROWS];    //     amax_r / 448

// ------------------------------ helpers ------------------------------------
__device__ __forceinline__ uint32_t s2u(const void* p) {
    return (uint32_t)__cvta_generic_to_shared(p);
}
__device__ __forceinline__ uint32_t swz(uint32_t o) { return o ^ ((o >> 3) & 0x70u); }

__device__ __forceinline__ void mbar_init(uint32_t a, uint32_t n) {
    asm volatile("mbarrier.init.shared.b64 [%0], %1;" :: "r"(a), "r"(n) : "memory");
}
__device__ __forceinline__ void mbar_expect(uint32_t a, uint32_t tx) {
    asm volatile("mbarrier.arrive.expect_tx.shared.b64 _, [%0], %1;"
                 :: "r"(a), "r"(tx) : "memory");
}
__device__ __forceinline__ void mbar_arrive(uint32_t a) {
    asm volatile("mbarrier.arrive.shared.b64 _, [%0];" :: "r"(a) : "memory");
}
__device__ __forceinline__ void mbar_wait(uint32_t a, uint32_t phase) {
    asm volatile(
        "{\n\t.reg .pred P;\n"
        "W%=:\n\t"
        "mbarrier.try_wait.parity.acquire.cta.shared::cta.b64 P, [%0], %1, 0x989680;\n\t"
        "@P bra D%=;\n\t"
        "bra W%=;\n"
        "D%=:\n\t}"
        :: "r"(a), "r"(phase) : "memory");
}
__device__ __forceinline__ void bulk_g2s(uint32_t dst, const void* src,
                                         uint32_t bytes, uint32_t bar) {
    asm volatile(
        "cp.async.bulk.shared::cluster.global.mbarrier::complete_tx::bytes "
        "[%0], [%1], %2, [%3];"
        :: "r"(dst), "l"(src), "r"(bytes), "r"(bar) : "memory");
}
__device__ __forceinline__ void ldm_x4(uint32_t* r, uint32_t addr) {
    asm volatile("ldmatrix.sync.aligned.m8n8.x4.shared.b16 {%0,%1,%2,%3}, [%4];"
                 : "=r"(r[0]), "=r"(r[1]), "=r"(r[2]), "=r"(r[3]) : "r"(addr));
}
__device__ __forceinline__ void mma16832(float* c, const uint32_t* a,
                                         uint32_t b0, uint32_t b1) {
    asm volatile(
        "mma.sync.aligned.m16n8k32.row.col.f32.e4m3.e4m3.f32 "
        "{%0,%1,%2,%3}, {%4,%5,%6,%7}, {%8,%9}, {%0,%1,%2,%3};"
        : "+f"(c[0]), "+f"(c[1]), "+f"(c[2]), "+f"(c[3])
        : "r"(a[0]), "r"(a[1]), "r"(a[2]), "r"(a[3]), "r"(b0), "r"(b1));
}
__device__ __forceinline__ uint32_t qfp8x4(float4 f, float q) {
    __nv_fp8x4_e4m3 v(make_float4(f.x * q, f.y * q, f.z * q, f.w * q));
    return *reinterpret_cast<uint32_t*>(&v);
}

// ------ pre-pass: f32 -> scaled e4m3, TILED+SWIZZLED blocks + norms --------
// x rows -> 128-row A blocks; p rows (r = p-0.5) -> 64-row B blocks.
__global__ void __launch_bounds__(128)
convq_kernel(const float* __restrict__ xsrc, const float* __restrict__ psrc) {
    const bool isx = (blockIdx.x < N_ROWS / 4);
    const int row  = (isx ? blockIdx.x : blockIdx.x - N_ROWS / 4) * 4
                   + (threadIdx.x >> 5);
    const int lane = threadIdx.x & 31;
    const float* src = isx ? xsrc : psrc;
    const float4* xr = reinterpret_cast<const float4*>(src + (size_t)row * DDIM);

    float4 f[2][4];
    float ss = 0.f, sm = 0.f, am = 0.f;
#pragma unroll
    for (int h = 0; h < 2; h++) {
        const int c = lane + h * 32;
#pragma unroll
        for (int j = 0; j < 4; j++) {
            float4 v = xr[c * 4 + j];
            ss += v.x * v.x + v.y * v.y + v.z * v.z + v.w * v.w;
            if (isx) {
                sm += v.x + v.y + v.z + v.w;
            } else {
                v.x -= 0.5f; v.y -= 0.5f; v.z -= 0.5f; v.w -= 0.5f;
            }
            f[h][j] = v;
            am = fmaxf(am, fmaxf(fmaxf(fabsf(v.x), fabsf(v.y)),
                                 fmaxf(fabsf(v.z), fabsf(v.w))));
        }
    }
#pragma unroll
    for (int o = 16; o; o >>= 1) {
        ss += __shfl_xor_sync(0xffffffffu, ss, o);
        am = fmaxf(am, __shfl_xor_sync(0xffffffffu, am, o));
        sm += __shfl_xor_sync(0xffffffffu, sm, o);
    }
    am = fmaxf(am, 1e-30f);
    const float q = 448.f / am;

    const int shift = isx ? 7 : 6;                 // A: 128-row, B: 64-row
    const int rt = row >> shift;
    const int rr = row & ((1 << shift) - 1);
    const int blk = isx ? A_BLOCK : B_BLOCK;
    uint8_t* base = (isx ? g_A : g_B) + (size_t)rt * K_TILES * blk;
#pragma unroll
    for (int h = 0; h < 2; h++) {
        const int c  = lane + h * 32;
        const int kt = c >> 3;
        const int cu = (c & 7) * 16;
        uint4 v;
        v.x = qfp8x4(f[h][0], q); v.y = qfp8x4(f[h][1], q);
        v.z = qfp8x4(f[h][2], q); v.w = qfp8x4(f[h][3], q);
        *reinterpret_cast<uint4*>(base + (size_t)kt * blk
                                  + swz((uint32_t)(rr * 128 + cu))) = v;
    }
    if (lane == 0) {
        if (isx) {
            g_xc[row] = ss - sm;
            g_sx[row] = 2.f * am * (1.f / 448.f);
        } else {
            g_psq[row] = ss;
            g_sp[row]  = am * (1.f / 448.f);
        }
    }
}

// --------------------------- main GEMM kernel ------------------------------
// CTA: 128 threads = 4 warps (2M x 2N); warp tile 64x32; 3 CTAs/SM.
__global__ void __launch_bounds__(128, 3)
gemm_kernel(float* __restrict__ out) {
    extern __shared__ char smem[];
    __shared__ __align__(8) uint64_t s_bar[2 * STAGES];   // FULL[3], EMPTY[3]

    const uint32_t sbase = (s2u(smem) + 1023u) & ~1023u;
    const uint32_t FULL  = s2u(s_bar);
    const uint32_t EMPTY = FULL + STAGES * 8;

    const int tid  = threadIdx.x;
    const int wid  = tid >> 5;
    const int lane = tid & 31;
    const int wm = (wid & 1) * 64;                 // M offset: 0 / 64
    const int wn = (wid >> 1) * 32;                // N offset: 0 / 32

    const uint8_t* Ag = g_A + (size_t)blockIdx.x * K_TILES * A_BLOCK;
    const uint8_t* Bg = g_B + (size_t)blockIdx.y * K_TILES * B_BLOCK;

    if (tid == 0) {
#pragma unroll
        for (int s = 0; s < STAGES; s++) {
            mbar_init(FULL + s * 8, 1);            // tx-based completion
            mbar_init(EMPTY + s * 8, 4);           // one arrive per warp
        }
    }
    __syncthreads();

    if (tid == 0) {
#pragma unroll
        for (int s = 0; s < STAGES - 1; s++) {
            const uint32_t fb  = FULL + s * 8;
            const uint32_t dst = sbase + s * STAGE_BYTES;
            mbar_expect(fb, STAGE_BYTES);
            bulk_g2s(dst,           Ag + (size_t)s * A_BLOCK, A_BLOCK, fb);
            bulk_g2s(dst + A_BLOCK, Bg + (size_t)s * B_BLOCK, B_BLOCK, fb);
        }
    }

    float acc[4][4][4];
#pragma unroll
    for (int i = 0; i < 4; i++)
#pragma unroll
        for (int j = 0; j < 4; j++)
#pragma unroll
            for (int r = 0; r < 4; r++) acc[i][j][r] = 0.f;

    const int lrow = lane & 15;
    const int lkb  = (lane >> 4) * 16;

    // Base relative addresses; kk XOR distributes (bits 5-6 vs >=11 disjoint).
    uint32_t AR0, BR0;
    {
        const int ra = wm + lrow;
        AR0 = (uint32_t)(ra * 128) + ((uint32_t)lkb ^ (uint32_t)((ra & 7) * 16));
        const int rb = wn + lrow;
        BR0 = (uint32_t)(rb * 128) + ((uint32_t)lkb ^ (uint32_t)((rb & 7) * 16));
    }

    uint32_t a[4][4];       // A fragments (reloaded per k32 step)
    uint32_t b[2][2][4];    // B fragments, double-buffered across k32 steps

    int pst = STAGES - 1, pph = 1;                 // producer cursor
    int cst = 0, cph = 0;                          // consumer cursor

    for (int kt = 0; kt < K_TILES; kt++) {
        // ---- producer: refill stage for kt+STAGES-1 ----------------------
        if (tid == 0 && kt + STAGES - 1 < K_TILES) {
            const int kf = kt + STAGES - 1;
            mbar_wait(EMPTY + pst * 8, (uint32_t)pph);
            const uint32_t fb  = FULL + pst * 8;
            const uint32_t dst = sbase + pst * STAGE_BYTES;
            mbar_expect(fb, STAGE_BYTES);
            bulk_g2s(dst,           Ag + (size_t)kf * A_BLOCK, A_BLOCK, fb);
            bulk_g2s(dst + A_BLOCK, Bg + (size_t)kf * B_BLOCK, B_BLOCK, fb);
            if (++pst == STAGES) { pst = 0; pph ^= 1; }
        }

        // ---- consumer: interleaved [ldm][mma] stream (R12) ---------------
        mbar_wait(FULL + cst * 8, (uint32_t)cph);
        const uint32_t sA = sbase + cst * STAGE_BYTES;
        const uint32_t sB = sA + A_BLOCK;

        // prime B bank 0 for kk=0
        ldm_x4(b[0][0], sB + BR0);
        ldm_x4(b[0][1], sB + BR0 + 2048);

#pragma unroll
        for (int kk = 0; kk < 4; kk++) {
            const int cur = kk & 1;
            const int nxt = cur ^ 1;
            const uint32_t av  = sA + (AR0 ^ (uint32_t)(kk << 5));
            const uint32_t bvn = sB + (BR0 ^ (uint32_t)((kk + 1) << 5));

            ldm_x4(a[0], av);
#pragma unroll
            for (int mi = 0; mi < 4; mi++) {
                if (mi < 3) {
                    ldm_x4(a[mi + 1], av + (uint32_t)((mi + 1) * 2048));
                } else if (kk < 3) {
                    ldm_x4(b[nxt][0], bvn);
                    ldm_x4(b[nxt][1], bvn + 2048);
                } else if (lane == 0) {
                    mbar_arrive(EMPTY + cst * 8);  // stage reads done
                }
#pragma unroll
                for (int nj = 0; nj < 2; nj++) {
                    mma16832(acc[mi][2 * nj + 0], a[mi],
                             b[cur][nj][0], b[cur][nj][2]);
                    mma16832(acc[mi][2 * nj + 1], a[mi],
                             b[cur][nj][1], b[cur][nj][3]);
                }
            }
        }
        if (++cst == STAGES) { cst = 0; cph ^= 1; }
    }

    // ---- fused dequant epilogue: out = xc + psq - sx*sp*acc  (x2 in sx) ----
    const int m0 = blockIdx.x * TILE_M;
    const int n0 = blockIdx.y * TILE_N;
    const int tr = lane >> 2;
    const int tc = (lane & 3) * 2;
#pragma unroll
    for (int mi = 0; mi < 4; mi++) {
        const int gm0 = m0 + wm + mi * 16 + tr;
        const float xc0 = g_xc[gm0],     sx0 = g_sx[gm0];
        const float xc1 = g_xc[gm0 + 8], sx1 = g_sx[gm0 + 8];
        float* o0 = out + (size_t)gm0 * C_ROWS + n0 + wn;
        float* o1 = o0 + (size_t)8 * C_ROWS;
#pragma unroll
        for (int ni = 0; ni < 4; ni++) {
            const int gc = n0 + wn + ni * 8 + tc;
            const float pq0 = __ldg(g_psq + gc),     sp0 = __ldg(g_sp + gc);
            const float pq1 = __ldg(g_psq + gc + 1), sp1 = __ldg(g_sp + gc + 1);
            float2 r0, r1;
            r0.x = fmaf(-sx0 * sp0, acc[mi][ni][0], xc0 + pq0);
            r0.y = fmaf(-sx0 * sp1, acc[mi][ni][1], xc0 + pq1);
            r1.x = fmaf(-sx1 * sp0, acc[mi][ni][2], xc1 + pq0);
            r1.y = fmaf(-sx1 * sp1, acc[mi][ni][3], xc1 + pq1);
            *reinterpret_cast<float2*>(o0 + ni * 8 + tc) = r0;
            *reinterpret_cast<float2*>(o1 + ni * 8 + tc) = r1;
        }
    }
}

// ------------------------------- launch ------------------------------------
extern "C" void kernel_launch(void* const* d_in, const int* in_sizes, int n_in,
                              void* d_out, int out_size) {
    const float* x = (const float*)d_in[0];       // [16384, 1024]
    const float* p = (const float*)d_in[1];       // [4096, 1024]
    float* out = (float*)d_out;                   // [16384, 4096]

    cudaFuncSetAttribute(gemm_kernel,
                         cudaFuncAttributeMaxDynamicSharedMemorySize, SMEM_DYN);

    convq_kernel<<<(N_ROWS + C_ROWS) / 4, 128>>>(x, p);
    gemm_kernel<<<dim3(N_ROWS / TILE_M, C_ROWS / TILE_N), 128, SMEM_DYN>>>(out);
}